// round 7
// baseline (speedup 1.0000x reference)
#include <cuda_runtime.h>
#include <cuda_bf16.h>
#include <cstdint>

// ============================================================
// Problem dims
// ============================================================
#define B_DIM 4096
#define IN_DIM 1024
#define H_DIM 1024
#define KK 2048            // IN + H (K of the GEMM)
#define NT 5120            // 5*H  (reordered: per-h tuple [i,f,o,c0,c1])

// GEMM tiling
#define BM 128
#define BN 160             // 32 h-tuples of 5 columns
#define BK 32
#define NCHUNK (KK / BK)   // 64
#define STAGES 3
#define THREADS 256

// smem: bf16 tiles with 40-element (80B) row pitch (conflict-free for LDSM)
#define PITCH_E 40
#define PITCH_B 80
#define A_TILE_B (BM * PITCH_B)          // 10240
#define B_TILE_B (BN * PITCH_B)          // 12800
#define OFF_AH 0
#define OFF_AL A_TILE_B
#define OFF_BH (2 * A_TILE_B)
#define OFF_BL (2 * A_TILE_B + B_TILE_B)
#define STAGE_B (2 * A_TILE_B + 2 * B_TILE_B)   // 46080
#define EPI_PITCH 164                    // floats, padded
#define SMEM_TOTAL (STAGES * STAGE_B)    // 138240 (>= 128*164*4 = 83968 for epilogue)

// ============================================================
// Scratch (__device__ globals: allocation-free rule)
// ============================================================
__device__ __nv_bfloat16 g_A_hi[(size_t)B_DIM * KK];
__device__ __nv_bfloat16 g_A_lo[(size_t)B_DIM * KK];
__device__ __nv_bfloat16 g_W_hi[(size_t)NT * KK];   // row n' = 5*h + j, j in {i,f,o,c0,c1}
__device__ __nv_bfloat16 g_W_lo[(size_t)NT * KK];

// ============================================================
// PTX helpers (baseline-family ISA only: no 'a'-suffix features)
// ============================================================
__device__ __forceinline__ uint32_t smem_u32(const void* p) {
    uint32_t a;
    asm("{ .reg .u64 t; cvta.to.shared.u64 t, %1; cvt.u32.u64 %0, t; }"
        : "=r"(a) : "l"(p));
    return a;
}

__device__ __forceinline__ void cp_async16(uint32_t s, const void* g) {
    asm volatile("cp.async.cg.shared.global [%0], [%1], 16;" :: "r"(s), "l"(g));
}
#define CP_COMMIT() asm volatile("cp.async.commit_group;" ::: "memory")
#define CP_WAIT1()  asm volatile("cp.async.wait_group 1;" ::: "memory")
#define CP_WAIT0()  asm volatile("cp.async.wait_group 0;" ::: "memory")

__device__ __forceinline__ void ldsm_x4(uint32_t* r, uint32_t addr) {
    asm volatile("ldmatrix.sync.aligned.m8n8.x4.shared.b16 {%0,%1,%2,%3}, [%4];"
                 : "=r"(r[0]), "=r"(r[1]), "=r"(r[2]), "=r"(r[3]) : "r"(addr));
}
__device__ __forceinline__ void ldsm_x2(uint32_t* r, uint32_t addr) {
    asm volatile("ldmatrix.sync.aligned.m8n8.x2.shared.b16 {%0,%1}, [%2];"
                 : "=r"(r[0]), "=r"(r[1]) : "r"(addr));
}
__device__ __forceinline__ void mma_bf16(float* c, const uint32_t* a, const uint32_t* b) {
    asm volatile(
        "mma.sync.aligned.m16n8k16.row.col.f32.bf16.bf16.f32 "
        "{%0,%1,%2,%3}, {%4,%5,%6,%7}, {%8,%9}, {%0,%1,%2,%3};"
        : "+f"(c[0]), "+f"(c[1]), "+f"(c[2]), "+f"(c[3])
        : "r"(a[0]), "r"(a[1]), "r"(a[2]), "r"(a[3]), "r"(b[0]), "r"(b[1]));
}

// bf16 hi/lo split of a float4 -> two __nv_bfloat162 pairs each
__device__ __forceinline__ void split4(float4 v, uint2& hi, uint2& lo) {
    __nv_bfloat16 h0 = __float2bfloat16(v.x);
    __nv_bfloat16 h1 = __float2bfloat16(v.y);
    __nv_bfloat16 h2 = __float2bfloat16(v.z);
    __nv_bfloat16 h3 = __float2bfloat16(v.w);
    __nv_bfloat16 l0 = __float2bfloat16(v.x - __bfloat162float(h0));
    __nv_bfloat16 l1 = __float2bfloat16(v.y - __bfloat162float(h1));
    __nv_bfloat16 l2 = __float2bfloat16(v.z - __bfloat162float(h2));
    __nv_bfloat16 l3 = __float2bfloat16(v.w - __bfloat162float(h3));
    __nv_bfloat162 ha; ha.x = h0; ha.y = h1;
    __nv_bfloat162 hb; hb.x = h2; hb.y = h3;
    __nv_bfloat162 la; la.x = l0; la.y = l1;
    __nv_bfloat162 lb; lb.x = l2; lb.y = l3;
    hi.x = *(uint32_t*)&ha; hi.y = *(uint32_t*)&hb;
    lo.x = *(uint32_t*)&la; lo.y = *(uint32_t*)&lb;
}

// ============================================================
// Kernel 1a: split combined [x | h_prev] into bf16 hi/lo, K-major
// ============================================================
__global__ __launch_bounds__(256)
void convA_kernel(const float* __restrict__ x, const float* __restrict__ h) {
    size_t i = (size_t)blockIdx.x * 256 + threadIdx.x;      // over B*KK/4
    if (i >= (size_t)B_DIM * KK / 4) return;
    size_t b  = i / (KK / 4);
    int    k4 = (int)(i % (KK / 4)) * 4;
    float4 v = (k4 < IN_DIM)
             ? *(const float4*)(x + b * IN_DIM + k4)
             : *(const float4*)(h + b * H_DIM + (k4 - IN_DIM));
    uint2 hi, lo;
    split4(v, hi, lo);
    *(uint2*)(g_A_hi + b * KK + k4) = hi;
    *(uint2*)(g_A_lo + b * KK + k4) = lo;
}

// Kernel 1b: split + REORDER W.  Row n' = 5*h + j:
//   j=0,1,2 -> Wg[j*1024 + h],  j=3,4 -> Wc[2*h + (j-3)]
__global__ __launch_bounds__(256)
void convW_kernel(const float* __restrict__ Wg, const float* __restrict__ Wc) {
    size_t i = (size_t)blockIdx.x * 256 + threadIdx.x;      // over NT*KK/4
    if (i >= (size_t)NT * KK / 4) return;
    size_t np = i / (KK / 4);
    int    k4 = (int)(i % (KK / 4)) * 4;
    int    hh = (int)(np / 5);
    int    j  = (int)(np % 5);
    const float* src = (j < 3) ? (Wg + ((size_t)j * H_DIM + hh) * KK + k4)
                               : (Wc + ((size_t)2 * hh + (j - 3)) * KK + k4);
    float4 v = *(const float4*)src;
    uint2 hi, lo;
    split4(v, hi, lo);
    *(uint2*)(g_W_hi + np * KK + k4) = hi;
    *(uint2*)(g_W_lo + np * KK + k4) = lo;
}

// ============================================================
// Kernel 2: fused GEMM (HMMA, 3-pass bf16 split) + LSTM epilogue
// ============================================================
__global__ __launch_bounds__(THREADS, 1)
void gemm_fused_kernel(const float* __restrict__ c_prev,
                       const float* __restrict__ bg, const float* __restrict__ bc,
                       const float* __restrict__ W1, const float* __restrict__ b1,
                       const float* __restrict__ W2, const float* __restrict__ b2,
                       float* __restrict__ out) {
    extern __shared__ __align__(128) char smem[];
    __shared__ float4 wk[32];     // {W1[k,0], W1[k,1], b1[k], W2[k]}
    __shared__ float  s_b2;

    const uint32_t sb = smem_u32(smem);
    const int tid  = threadIdx.x;
    const int wid  = tid >> 5;
    const int lane = tid & 31;
    const int wm   = wid >> 2;          // 0..1  (M warps)
    const int wn   = wid & 3;           // 0..3  (N warps)
    const int m0   = blockIdx.y * BM;
    const int hb0  = blockIdx.x * 32;   // first h of this CTA
    const int n0   = hb0 * 5;           // first W' row

    if (tid < 32) wk[tid] = make_float4(W1[2 * tid], W1[2 * tid + 1], b1[tid], W2[tid]);
    if (tid == 0) s_b2 = b2[0];

    // ---- cp.async source/dest offsets (per thread) ----
    // A: 512 vec16 per tile (128 rows x 4), 2 tiles; B: 640 per tile (160 x 4), 2 tiles.
    // smem row pitch 80B -> rows 0..7 mod 128B = {0,80,32,112,64,16,96,48}: LDSM conflict-free.
    uint32_t sA[2]; size_t gA[2];
#pragma unroll
    for (int j = 0; j < 2; ++j) {
        int v = tid + j * 256;                  // 0..511
        int r = v >> 2, c = v & 3;
        sA[j] = (uint32_t)(r * PITCH_B + c * 16);
        gA[j] = (size_t)(m0 + r) * KK + c * 8;
    }
    uint32_t sB[3]; size_t gB[3];
#pragma unroll
    for (int j = 0; j < 3; ++j) {
        int v = tid + j * 256;                  // 0..767 (guard < 640)
        int r = v >> 2, c = v & 3;
        sB[j] = (uint32_t)(r * PITCH_B + c * 16);
        gB[j] = (size_t)(n0 + r) * KK + c * 8;
    }
    const bool bok = (tid < 128);               // j==2 guard (512+tid < 640)

    // ---- LDSM base addresses ----
    // A frag (mi, s): addr = stageA + aoff + mi*16*80 + s*32
    const uint32_t aoff = (uint32_t)((wm * 64 + (lane & 15)) * PITCH_B + (lane >> 4) * 16);
    // B frag (ni, s): addr = stageB + boff + ni*8*80 + s*32
    const uint32_t boff = (uint32_t)((wn * 40 + (lane & 7)) * PITCH_B + ((lane >> 3) & 1) * 16);

    float acc[4][5][4];
#pragma unroll
    for (int mi = 0; mi < 4; ++mi)
#pragma unroll
        for (int ni = 0; ni < 5; ++ni)
#pragma unroll
            for (int q = 0; q < 4; ++q) acc[mi][ni][q] = 0.f;

    // ---- pipeline prologue: stages 0,1 ----
#pragma unroll
    for (int pc = 0; pc < 2; ++pc) {
        const uint32_t st = sb + pc * STAGE_B;
        const int k0 = pc * BK;
#pragma unroll
        for (int j = 0; j < 2; ++j) {
            cp_async16(st + OFF_AH + sA[j], g_A_hi + gA[j] + k0);
            cp_async16(st + OFF_AL + sA[j], g_A_lo + gA[j] + k0);
        }
#pragma unroll
        for (int j = 0; j < 3; ++j) {
            if (j < 2 || bok) {
                cp_async16(st + OFF_BH + sB[j], g_W_hi + gB[j] + k0);
                cp_async16(st + OFF_BL + sB[j], g_W_lo + gB[j] + k0);
            }
        }
        CP_COMMIT();
    }

    // ---- main loop ----
    for (int kc = 0; kc < NCHUNK; ++kc) {
        CP_WAIT1();
        __syncthreads();

        // issue stage kc+2 (buffer was consumed in iter kc-1; all warps passed the sync)
        {
            const int kn = kc + 2;
            if (kn < NCHUNK) {
                const uint32_t st = sb + (kn % STAGES) * STAGE_B;
                const int k0 = kn * BK;
#pragma unroll
                for (int j = 0; j < 2; ++j) {
                    cp_async16(st + OFF_AH + sA[j], g_A_hi + gA[j] + k0);
                    cp_async16(st + OFF_AL + sA[j], g_A_lo + gA[j] + k0);
                }
#pragma unroll
                for (int j = 0; j < 3; ++j) {
                    if (j < 2 || bok) {
                        cp_async16(st + OFF_BH + sB[j], g_W_hi + gB[j] + k0);
                        cp_async16(st + OFF_BL + sB[j], g_W_lo + gB[j] + k0);
                    }
                }
            }
            CP_COMMIT();   // commit (possibly empty) to keep group accounting uniform
        }

        const uint32_t st = sb + (kc % STAGES) * STAGE_B;
#pragma unroll
        for (int s = 0; s < 2; ++s) {           // two k16 steps per BK=32
            uint32_t ah[4][4], al[4][4], bh[5][2], bl[5][2];
#pragma unroll
            for (int mi = 0; mi < 4; ++mi) {
                ldsm_x4(ah[mi], st + OFF_AH + aoff + mi * 16 * PITCH_B + s * 32);
                ldsm_x4(al[mi], st + OFF_AL + aoff + mi * 16 * PITCH_B + s * 32);
            }
#pragma unroll
            for (int ni = 0; ni < 5; ++ni) {
                ldsm_x2(bh[ni], st + OFF_BH + boff + ni * 8 * PITCH_B + s * 32);
                ldsm_x2(bl[ni], st + OFF_BL + boff + ni * 8 * PITCH_B + s * 32);
            }
#pragma unroll
            for (int mi = 0; mi < 4; ++mi)
#pragma unroll
                for (int ni = 0; ni < 5; ++ni) {
                    mma_bf16(acc[mi][ni], ah[mi], bh[ni]);   // hh
                    mma_bf16(acc[mi][ni], ah[mi], bl[ni]);   // hl
                    mma_bf16(acc[mi][ni], al[mi], bh[ni]);   // lh
                }
        }
    }
    CP_WAIT0();
    __syncthreads();    // done with stage buffers -> reuse smem for epilogue

    // ---- spill accumulators to smem [128][160] (pitch 164 floats) ----
    float* sf = (float*)smem;
    {
        const int r0 = wm * 64 + (lane >> 2);
        const int c0 = wn * 40 + (lane & 3) * 2;
#pragma unroll
        for (int mi = 0; mi < 4; ++mi)
#pragma unroll
            for (int ni = 0; ni < 5; ++ni) {
                const int rr = r0 + mi * 16;
                const int cc = c0 + ni * 8;
                sf[rr * EPI_PITCH + cc]            = acc[mi][ni][0];
                sf[rr * EPI_PITCH + cc + 1]        = acc[mi][ni][1];
                sf[(rr + 8) * EPI_PITCH + cc]      = acc[mi][ni][2];
                sf[(rr + 8) * EPI_PITCH + cc + 1]  = acc[mi][ni][3];
            }
    }
    __syncthreads();

    // ---- fused LSTM epilogue: 128 rows x 32 h per CTA ----
    for (int i = tid; i < BM * 32; i += THREADS) {
        const int r  = i >> 5;          // local m row
        const int hl = i & 31;          // local h
        const int b  = m0 + r;
        const int h  = hb0 + hl;
        const float* row = sf + r * EPI_PITCH + hl * 5;

        float iv = 1.f / (1.f + __expf(-(row[0] + bg[h])));
        float fv = 1.f / (1.f + __expf(-(row[1] + bg[H_DIM + h])));
        float ov = 1.f / (1.f + __expf(-(row[2] + bg[2 * H_DIM + h])));
        float p0 = row[3] + bc[2 * h];
        float p1 = row[4] + bc[2 * h + 1];

        float gsum = s_b2;
#pragma unroll
        for (int k = 0; k < 32; ++k) {
            float4 w = wk[k];
            float hid = fmaxf(w.x * p0 + w.y * p1 + w.z, 0.f);
            gsum += w.w * hid;
        }

        float c = fv * c_prev[(size_t)b * H_DIM + h] + iv * gsum;
        out[(size_t)b * H_DIM + h] = ov * tanhf(c);
        out[(size_t)B_DIM * H_DIM + (size_t)b * H_DIM + h] = c;
    }
}

// ============================================================
// Launch
// ============================================================
extern "C" void kernel_launch(void* const* d_in, const int* in_sizes, int n_in,
                              void* d_out, int out_size) {
    const float* x      = (const float*)d_in[0];
    const float* h_prev = (const float*)d_in[1];
    const float* c_prev = (const float*)d_in[2];
    const float* Wg     = (const float*)d_in[3];
    const float* bg     = (const float*)d_in[4];
    const float* Wc     = (const float*)d_in[5];
    const float* bc     = (const float*)d_in[6];
    const float* W1     = (const float*)d_in[7];
    const float* b1     = (const float*)d_in[8];
    const float* W2     = (const float*)d_in[9];
    const float* b2     = (const float*)d_in[10];
    float* out = (float*)d_out;

    convA_kernel<<<(int)(((size_t)B_DIM * KK / 4 + 255) / 256), 256>>>(x, h_prev);
    convW_kernel<<<(int)(((size_t)NT * KK / 4 + 255) / 256), 256>>>(Wg, Wc);

    cudaFuncSetAttribute(gemm_fused_kernel,
                         cudaFuncAttributeMaxDynamicSharedMemorySize, SMEM_TOTAL);
    dim3 grid(H_DIM / 32, B_DIM / BM);   // 32 x 32 = 1024 CTAs
    gemm_fused_kernel<<<grid, THREADS, SMEM_TOTAL>>>(c_prev, bg, bc, W1, b1, W2, b2, out);
}

// round 10
// speedup vs baseline: 1.3069x; 1.3069x over previous
#include <cuda_runtime.h>
#include <cuda_fp16.h>
#include <cstdint>

// ============================================================
// Problem dims
// ============================================================
#define B_DIM 4096
#define IN_DIM 1024
#define H_DIM 1024
#define KK 2048            // IN + H (K of the GEMM)
#define NT 5120            // 5*H  (reordered: per-h tuple [i,f,o,c0,c1])

// GEMM tiling
#define BM 128
#define BN 160             // 32 h-tuples of 5 columns
#define BK 32
#define NCHUNK (KK / BK)   // 64
#define STAGES 3
#define THREADS 256

// smem: fp16 tiles with 40-element (80B) row pitch (conflict-free for LDSM)
#define PITCH_B 80
#define A_TILE_B (BM * PITCH_B)          // 10240
#define B_TILE_B (BN * PITCH_B)          // 12800
#define OFF_AH 0
#define OFF_AL A_TILE_B
#define OFF_B  (2 * A_TILE_B)
#define STAGE_B (2 * A_TILE_B + B_TILE_B)   // 33280
#define EPI_PITCH 164                    // floats, padded
#define SMEM_TOTAL (STAGES * STAGE_B)    // 99840 (>= 128*164*4 = 83968 for epilogue)

// ============================================================
// Scratch (__device__ globals: allocation-free rule)
// ============================================================
__device__ __half g_A_hi[(size_t)B_DIM * KK];
__device__ __half g_A_lo[(size_t)B_DIM * KK];
__device__ __half g_W[(size_t)NT * KK];   // row n' = 5*h + j, j in {i,f,o,c0,c1}

// ============================================================
// PTX helpers (baseline-family ISA only: no 'a'-suffix features)
// ============================================================
__device__ __forceinline__ uint32_t smem_u32(const void* p) {
    uint32_t a;
    asm("{ .reg .u64 t; cvta.to.shared.u64 t, %1; cvt.u32.u64 %0, t; }"
        : "=r"(a) : "l"(p));
    return a;
}

__device__ __forceinline__ void cp_async16(uint32_t s, const void* g) {
    asm volatile("cp.async.cg.shared.global [%0], [%1], 16;" :: "r"(s), "l"(g));
}
#define CP_COMMIT() asm volatile("cp.async.commit_group;" ::: "memory")
#define CP_WAIT1()  asm volatile("cp.async.wait_group 1;" ::: "memory")
#define CP_WAIT0()  asm volatile("cp.async.wait_group 0;" ::: "memory")

__device__ __forceinline__ void ldsm_x4(uint32_t* r, uint32_t addr) {
    asm volatile("ldmatrix.sync.aligned.m8n8.x4.shared.b16 {%0,%1,%2,%3}, [%4];"
                 : "=r"(r[0]), "=r"(r[1]), "=r"(r[2]), "=r"(r[3]) : "r"(addr));
}
__device__ __forceinline__ void ldsm_x2(uint32_t* r, uint32_t addr) {
    asm volatile("ldmatrix.sync.aligned.m8n8.x2.shared.b16 {%0,%1}, [%2];"
                 : "=r"(r[0]), "=r"(r[1]) : "r"(addr));
}
__device__ __forceinline__ void mma_fp16(float* c, const uint32_t* a, const uint32_t* b) {
    asm volatile(
        "mma.sync.aligned.m16n8k16.row.col.f32.f16.f16.f32 "
        "{%0,%1,%2,%3}, {%4,%5,%6,%7}, {%8,%9}, {%0,%1,%2,%3};"
        : "+f"(c[0]), "+f"(c[1]), "+f"(c[2]), "+f"(c[3])
        : "r"(a[0]), "r"(a[1]), "r"(a[2]), "r"(a[3]), "r"(b[0]), "r"(b[1]));
}

// fp16 hi/lo split of a float4
__device__ __forceinline__ void split4h(float4 v, uint2& hi, uint2& lo) {
    __half h0 = __float2half(v.x);
    __half h1 = __float2half(v.y);
    __half h2 = __float2half(v.z);
    __half h3 = __float2half(v.w);
    __half l0 = __float2half(v.x - __half2float(h0));
    __half l1 = __float2half(v.y - __half2float(h1));
    __half l2 = __float2half(v.z - __half2float(h2));
    __half l3 = __float2half(v.w - __half2float(h3));
    __half2 ha = __halves2half2(h0, h1), hb = __halves2half2(h2, h3);
    __half2 la = __halves2half2(l0, l1), lb = __halves2half2(l2, l3);
    hi.x = *(uint32_t*)&ha; hi.y = *(uint32_t*)&hb;
    lo.x = *(uint32_t*)&la; lo.y = *(uint32_t*)&lb;
}

// ============================================================
// Kernel 1a: split combined [x | h_prev] into fp16 hi/lo, K-major
// ============================================================
__global__ __launch_bounds__(256)
void convA_kernel(const float* __restrict__ x, const float* __restrict__ h) {
    size_t i = (size_t)blockIdx.x * 256 + threadIdx.x;      // over B*KK/4
    if (i >= (size_t)B_DIM * KK / 4) return;
    size_t b  = i / (KK / 4);
    int    k4 = (int)(i % (KK / 4)) * 4;
    float4 v = (k4 < IN_DIM)
             ? *(const float4*)(x + b * IN_DIM + k4)
             : *(const float4*)(h + b * H_DIM + (k4 - IN_DIM));
    uint2 hi, lo;
    split4h(v, hi, lo);
    *(uint2*)(g_A_hi + b * KK + k4) = hi;
    *(uint2*)(g_A_lo + b * KK + k4) = lo;
}

// Kernel 1b: fp16-round + REORDER W.  Row n' = 5*h + j:
//   j=0,1,2 -> Wg[j*1024 + h],  j=3,4 -> Wc[2*h + (j-3)]
__global__ __launch_bounds__(256)
void convW_kernel(const float* __restrict__ Wg, const float* __restrict__ Wc) {
    size_t i = (size_t)blockIdx.x * 256 + threadIdx.x;      // over NT*KK/4
    if (i >= (size_t)NT * KK / 4) return;
    size_t np = i / (KK / 4);
    int    k4 = (int)(i % (KK / 4)) * 4;
    int    hh = (int)(np / 5);
    int    j  = (int)(np % 5);
    const float* src = (j < 3) ? (Wg + ((size_t)j * H_DIM + hh) * KK + k4)
                               : (Wc + ((size_t)2 * hh + (j - 3)) * KK + k4);
    float4 v = *(const float4*)src;
    __half2 a = __halves2half2(__float2half(v.x), __float2half(v.y));
    __half2 b = __halves2half2(__float2half(v.z), __float2half(v.w));
    uint2 o;
    o.x = *(uint32_t*)&a; o.y = *(uint32_t*)&b;
    *(uint2*)(g_W + np * KK + k4) = o;
}

// ============================================================
// Kernel 2: fused GEMM (HMMA, 2-pass fp16 split-A) + LSTM epilogue
// ============================================================
__global__ __launch_bounds__(THREADS, 1)
void gemm_fused_kernel(const float* __restrict__ c_prev,
                       const float* __restrict__ bg, const float* __restrict__ bc,
                       const float* __restrict__ W1, const float* __restrict__ b1,
                       const float* __restrict__ W2, const float* __restrict__ b2,
                       float* __restrict__ out) {
    extern __shared__ __align__(128) char smem[];
    __shared__ float4 wk[32];     // {W1[k,0], W1[k,1], b1[k], W2[k]}
    __shared__ float  s_b2;

    const uint32_t sb = smem_u32(smem);
    const int tid  = threadIdx.x;
    const int wid  = tid >> 5;
    const int lane = tid & 31;
    const int wm   = wid >> 2;          // 0..1  (M warps)
    const int wn   = wid & 3;           // 0..3  (N warps)
    const int m0   = blockIdx.y * BM;
    const int hb0  = blockIdx.x * 32;   // first h of this CTA
    const int n0   = hb0 * 5;           // first W' row

    if (tid < 32) wk[tid] = make_float4(W1[2 * tid], W1[2 * tid + 1], b1[tid], W2[tid]);
    if (tid == 0) s_b2 = b2[0];

    // ---- cp.async source/dest offsets (per thread) ----
    // A: 512 vec16 per tile (128 rows x 4), hi+lo tiles; B: 640 (160 x 4), 1 tile.
    // smem row pitch 80B -> rows 0..7 mod 128B = {0,80,32,112,64,16,96,48}: LDSM conflict-free.
    uint32_t sA[2]; size_t gA[2];
#pragma unroll
    for (int j = 0; j < 2; ++j) {
        int v = tid + j * 256;                  // 0..511
        int r = v >> 2, c = v & 3;
        sA[j] = (uint32_t)(r * PITCH_B + c * 16);
        gA[j] = (size_t)(m0 + r) * KK + c * 8;
    }
    uint32_t sB[3]; size_t gB[3];
#pragma unroll
    for (int j = 0; j < 3; ++j) {
        int v = tid + j * 256;                  // 0..767 (guard < 640)
        int r = v >> 2, c = v & 3;
        sB[j] = (uint32_t)(r * PITCH_B + c * 16);
        gB[j] = (size_t)(n0 + r) * KK + c * 8;
    }
    const bool bok = (tid < 128);               // j==2 guard (512+tid < 640)

    // ---- LDSM base addresses ----
    const uint32_t aoff = (uint32_t)((wm * 64 + (lane & 15)) * PITCH_B + (lane >> 4) * 16);
    const uint32_t boff = (uint32_t)((wn * 40 + (lane & 7)) * PITCH_B + ((lane >> 3) & 1) * 16);

    float acc[4][5][4];
#pragma unroll
    for (int mi = 0; mi < 4; ++mi)
#pragma unroll
        for (int ni = 0; ni < 5; ++ni)
#pragma unroll
            for (int q = 0; q < 4; ++q) acc[mi][ni][q] = 0.f;

    // ---- pipeline prologue: stages 0,1 ----
#pragma unroll
    for (int pc = 0; pc < 2; ++pc) {
        const uint32_t st = sb + pc * STAGE_B;
        const int k0 = pc * BK;
#pragma unroll
        for (int j = 0; j < 2; ++j) {
            cp_async16(st + OFF_AH + sA[j], g_A_hi + gA[j] + k0);
            cp_async16(st + OFF_AL + sA[j], g_A_lo + gA[j] + k0);
        }
#pragma unroll
        for (int j = 0; j < 3; ++j) {
            if (j < 2 || bok) cp_async16(st + OFF_B + sB[j], g_W + gB[j] + k0);
        }
        CP_COMMIT();
    }

    // ---- main loop ----
    for (int kc = 0; kc < NCHUNK; ++kc) {
        CP_WAIT1();
        __syncthreads();

        // issue stage kc+2 (buffer consumed in iter kc-1; all warps passed the sync)
        {
            const int kn = kc + 2;
            if (kn < NCHUNK) {
                const uint32_t st = sb + (kn % STAGES) * STAGE_B;
                const int k0 = kn * BK;
#pragma unroll
                for (int j = 0; j < 2; ++j) {
                    cp_async16(st + OFF_AH + sA[j], g_A_hi + gA[j] + k0);
                    cp_async16(st + OFF_AL + sA[j], g_A_lo + gA[j] + k0);
                }
#pragma unroll
                for (int j = 0; j < 3; ++j) {
                    if (j < 2 || bok) cp_async16(st + OFF_B + sB[j], g_W + gB[j] + k0);
                }
            }
            CP_COMMIT();   // commit (possibly empty) to keep group accounting uniform
        }

        const uint32_t st = sb + (kc % STAGES) * STAGE_B;
#pragma unroll
        for (int s = 0; s < 2; ++s) {           // two k16 steps per BK=32
            uint32_t ah[4][4], al[4][4], bv[5][2];
#pragma unroll
            for (int mi = 0; mi < 4; ++mi) {
                ldsm_x4(ah[mi], st + OFF_AH + aoff + mi * 16 * PITCH_B + s * 32);
                ldsm_x4(al[mi], st + OFF_AL + aoff + mi * 16 * PITCH_B + s * 32);
            }
#pragma unroll
            for (int ni = 0; ni < 5; ++ni)
                ldsm_x2(bv[ni], st + OFF_B + boff + ni * 8 * PITCH_B + s * 32);
#pragma unroll
            for (int mi = 0; mi < 4; ++mi)
#pragma unroll
                for (int ni = 0; ni < 5; ++ni) {
                    mma_fp16(acc[mi][ni], ah[mi], bv[ni]);   // hi pass
                    mma_fp16(acc[mi][ni], al[mi], bv[ni]);   // lo pass
                }
        }
    }
    CP_WAIT0();
    __syncthreads();    // done with stage buffers -> reuse smem for epilogue

    // ---- spill accumulators to smem [128][160] (pitch 164 floats) ----
    float* sf = (float*)smem;
    {
        const int r0 = wm * 64 + (lane >> 2);
        const int c0 = wn * 40 + (lane & 3) * 2;
#pragma unroll
        for (int mi = 0; mi < 4; ++mi)
#pragma unroll
            for (int ni = 0; ni < 5; ++ni) {
                const int rr = r0 + mi * 16;
                const int cc = c0 + ni * 8;
                sf[rr * EPI_PITCH + cc]            = acc[mi][ni][0];
                sf[rr * EPI_PITCH + cc + 1]        = acc[mi][ni][1];
                sf[(rr + 8) * EPI_PITCH + cc]      = acc[mi][ni][2];
                sf[(rr + 8) * EPI_PITCH + cc + 1]  = acc[mi][ni][3];
            }
    }
    __syncthreads();

    // ---- fused LSTM epilogue: 128 rows x 32 h per CTA ----
    for (int i = tid; i < BM * 32; i += THREADS) {
        const int r  = i >> 5;          // local m row
        const int hl = i & 31;          // local h
        const int b  = m0 + r;
        const int h  = hb0 + hl;
        const float* row = sf + r * EPI_PITCH + hl * 5;

        float iv = 1.f / (1.f + __expf(-(row[0] + bg[h])));
        float fv = 1.f / (1.f + __expf(-(row[1] + bg[H_DIM + h])));
        float ov = 1.f / (1.f + __expf(-(row[2] + bg[2 * H_DIM + h])));
        float p0 = row[3] + bc[2 * h];
        float p1 = row[4] + bc[2 * h + 1];

        float gsum = s_b2;
#pragma unroll
        for (int k = 0; k < 32; ++k) {
            float4 w = wk[k];
            float hid = fmaxf(w.x * p0 + w.y * p1 + w.z, 0.f);
            gsum += w.w * hid;
        }

        float c = fv * c_prev[(size_t)b * H_DIM + h] + iv * gsum;
        out[(size_t)b * H_DIM + h] = ov * tanhf(c);
        out[(size_t)B_DIM * H_DIM + (size_t)b * H_DIM + h] = c;
    }
}

// ============================================================
// Launch
// ============================================================
extern "C" void kernel_launch(void* const* d_in, const int* in_sizes, int n_in,
                              void* d_out, int out_size) {
    const float* x      = (const float*)d_in[0];
    const float* h_prev = (const float*)d_in[1];
    const float* c_prev = (const float*)d_in[2];
    const float* Wg     = (const float*)d_in[3];
    const float* bg     = (const float*)d_in[4];
    const float* Wc     = (const float*)d_in[5];
    const float* bc     = (const float*)d_in[6];
    const float* W1     = (const float*)d_in[7];
    const float* b1     = (const float*)d_in[8];
    const float* W2     = (const float*)d_in[9];
    const float* b2     = (const float*)d_in[10];
    float* out = (float*)d_out;

    convA_kernel<<<(int)(((size_t)B_DIM * KK / 4 + 255) / 256), 256>>>(x, h_prev);
    convW_kernel<<<(int)(((size_t)NT * KK / 4 + 255) / 256), 256>>>(Wg, Wc);

    cudaFuncSetAttribute(gemm_fused_kernel,
                         cudaFuncAttributeMaxDynamicSharedMemorySize, SMEM_TOTAL);
    dim3 grid(H_DIM / 32, B_DIM / BM);   // 32 x 32 = 1024 CTAs
    gemm_fused_kernel<<<grid, THREADS, SMEM_TOTAL>>>(c_prev, bg, bc, W1, b1, W2, b2, out);
}

// round 11
// speedup vs baseline: 2.0688x; 1.5829x over previous
#include <cuda_runtime.h>
#include <cuda_fp16.h>
#include <cstdint>

// ============================================================
// Problem dims
// ============================================================
#define B_DIM 4096
#define IN_DIM 1024
#define H_DIM 1024
#define KK 2048            // IN + H (K of the GEMM)
#define NT 5120            // 5*H  (reordered: per-h tuple [i,f,o,c0,c1])

// GEMM tiling
#define BM 128
#define BN 160             // 32 h-tuples of 5 columns
#define BK 32
#define NCHUNK (KK / BK)   // 64
#define STAGES 4
#define THREADS 256

// smem: fp16 tiles with 40-element (80B) row pitch (conflict-free for LDSM)
#define PITCH_B 80
#define A_TILE_B (BM * PITCH_B)          // 10240
#define B_TILE_B (BN * PITCH_B)          // 12800
#define OFF_A 0
#define OFF_B A_TILE_B
#define STAGE_B (A_TILE_B + B_TILE_B)    // 23040
#define EPI_PITCH 164                    // floats, padded
// max(4 stages = 92160, epilogue 128*164*4 = 83968)
#define SMEM_TOTAL (STAGES * STAGE_B)    // 92160

// ============================================================
// Scratch (__device__ globals: allocation-free rule)
// ============================================================
__device__ __half g_A[(size_t)B_DIM * KK];
__device__ __half g_W[(size_t)NT * KK];   // row n' = 5*h + j, j in {i,f,o,c0,c1}

// ============================================================
// PTX helpers (baseline-family ISA only: no 'a'-suffix features)
// ============================================================
__device__ __forceinline__ uint32_t smem_u32(const void* p) {
    uint32_t a;
    asm("{ .reg .u64 t; cvta.to.shared.u64 t, %1; cvt.u32.u64 %0, t; }"
        : "=r"(a) : "l"(p));
    return a;
}

__device__ __forceinline__ void cp_async16(uint32_t s, const void* g) {
    asm volatile("cp.async.cg.shared.global [%0], [%1], 16;" :: "r"(s), "l"(g));
}
#define CP_COMMIT() asm volatile("cp.async.commit_group;" ::: "memory")
#define CP_WAIT2()  asm volatile("cp.async.wait_group 2;" ::: "memory")
#define CP_WAIT0()  asm volatile("cp.async.wait_group 0;" ::: "memory")

__device__ __forceinline__ void ldsm_x4(uint32_t* r, uint32_t addr) {
    asm volatile("ldmatrix.sync.aligned.m8n8.x4.shared.b16 {%0,%1,%2,%3}, [%4];"
                 : "=r"(r[0]), "=r"(r[1]), "=r"(r[2]), "=r"(r[3]) : "r"(addr));
}
__device__ __forceinline__ void ldsm_x2(uint32_t* r, uint32_t addr) {
    asm volatile("ldmatrix.sync.aligned.m8n8.x2.shared.b16 {%0,%1}, [%2];"
                 : "=r"(r[0]), "=r"(r[1]) : "r"(addr));
}
__device__ __forceinline__ void mma_fp16(float* c, const uint32_t* a, const uint32_t* b) {
    asm volatile(
        "mma.sync.aligned.m16n8k16.row.col.f32.f16.f16.f32 "
        "{%0,%1,%2,%3}, {%4,%5,%6,%7}, {%8,%9}, {%0,%1,%2,%3};"
        : "+f"(c[0]), "+f"(c[1]), "+f"(c[2]), "+f"(c[3])
        : "r"(a[0]), "r"(a[1]), "r"(a[2]), "r"(a[3]), "r"(b[0]), "r"(b[1]));
}

// round float4 -> 4 fp16 packed in uint2
__device__ __forceinline__ uint2 round4h(float4 v) {
    __half2 a = __halves2half2(__float2half(v.x), __float2half(v.y));
    __half2 b = __halves2half2(__float2half(v.z), __float2half(v.w));
    uint2 o;
    o.x = *(uint32_t*)&a; o.y = *(uint32_t*)&b;
    return o;
}

// ============================================================
// Kernel 1a: round combined [x | h_prev] to fp16, K-major
// ============================================================
__global__ __launch_bounds__(256)
void convA_kernel(const float* __restrict__ x, const float* __restrict__ h) {
    size_t i = (size_t)blockIdx.x * 256 + threadIdx.x;      // over B*KK/4
    if (i >= (size_t)B_DIM * KK / 4) return;
    size_t b  = i / (KK / 4);
    int    k4 = (int)(i % (KK / 4)) * 4;
    float4 v = (k4 < IN_DIM)
             ? *(const float4*)(x + b * IN_DIM + k4)
             : *(const float4*)(h + b * H_DIM + (k4 - IN_DIM));
    *(uint2*)(g_A + b * KK + k4) = round4h(v);
}

// Kernel 1b: fp16-round + REORDER W.  Row n' = 5*h + j:
//   j=0,1,2 -> Wg[j*1024 + h],  j=3,4 -> Wc[2*h + (j-3)]
__global__ __launch_bounds__(256)
void convW_kernel(const float* __restrict__ Wg, const float* __restrict__ Wc) {
    size_t i = (size_t)blockIdx.x * 256 + threadIdx.x;      // over NT*KK/4
    if (i >= (size_t)NT * KK / 4) return;
    size_t np = i / (KK / 4);
    int    k4 = (int)(i % (KK / 4)) * 4;
    int    hh = (int)(np / 5);
    int    j  = (int)(np % 5);
    const float* src = (j < 3) ? (Wg + ((size_t)j * H_DIM + hh) * KK + k4)
                               : (Wc + ((size_t)2 * hh + (j - 3)) * KK + k4);
    *(uint2*)(g_W + np * KK + k4) = round4h(*(const float4*)src);
}

// ============================================================
// Kernel 2: fused GEMM (HMMA, 1-pass fp16) + LSTM epilogue
// ============================================================
__global__ __launch_bounds__(THREADS, 1)
void gemm_fused_kernel(const float* __restrict__ c_prev,
                       const float* __restrict__ bg, const float* __restrict__ bc,
                       const float* __restrict__ W1, const float* __restrict__ b1,
                       const float* __restrict__ W2, const float* __restrict__ b2,
                       float* __restrict__ out) {
    extern __shared__ __align__(128) char smem[];
    __shared__ float4 wk[32];     // {W1[k,0], W1[k,1], b1[k], W2[k]}
    __shared__ float  s_b2;

    const uint32_t sb = smem_u32(smem);
    const int tid  = threadIdx.x;
    const int wid  = tid >> 5;
    const int lane = tid & 31;
    const int wm   = wid >> 2;          // 0..1  (M warps)
    const int wn   = wid & 3;           // 0..3  (N warps)
    const int m0   = blockIdx.y * BM;
    const int hb0  = blockIdx.x * 32;   // first h of this CTA
    const int n0   = hb0 * 5;           // first W' row

    if (tid < 32) wk[tid] = make_float4(W1[2 * tid], W1[2 * tid + 1], b1[tid], W2[tid]);
    if (tid == 0) s_b2 = b2[0];

    // ---- cp.async source/dest offsets (per thread) ----
    // A: 512 vec16 per tile (128 rows x 4); B: 640 (160 x 4).
    // smem row pitch 80B -> rows 0..7 mod 128B = {0,80,32,112,64,16,96,48}: LDSM conflict-free.
    uint32_t sA[2]; size_t gA[2];
#pragma unroll
    for (int j = 0; j < 2; ++j) {
        int v = tid + j * 256;                  // 0..511
        int r = v >> 2, c = v & 3;
        sA[j] = (uint32_t)(r * PITCH_B + c * 16);
        gA[j] = (size_t)(m0 + r) * KK + c * 8;
    }
    uint32_t sB[3]; size_t gB[3];
#pragma unroll
    for (int j = 0; j < 3; ++j) {
        int v = tid + j * 256;                  // 0..767 (guard < 640)
        int r = v >> 2, c = v & 3;
        sB[j] = (uint32_t)(r * PITCH_B + c * 16);
        gB[j] = (size_t)(n0 + r) * KK + c * 8;
    }
    const bool bok = (tid < 128);               // j==2 guard (512+tid < 640)

    // ---- LDSM base addresses ----
    const uint32_t aoff = (uint32_t)((wm * 64 + (lane & 15)) * PITCH_B + (lane >> 4) * 16);
    const uint32_t boff = (uint32_t)((wn * 40 + (lane & 7)) * PITCH_B + ((lane >> 3) & 1) * 16);

    float acc[4][5][4];
#pragma unroll
    for (int mi = 0; mi < 4; ++mi)
#pragma unroll
        for (int ni = 0; ni < 5; ++ni)
#pragma unroll
            for (int q = 0; q < 4; ++q) acc[mi][ni][q] = 0.f;

    // ---- pipeline prologue: stages 0..2 ----
#pragma unroll
    for (int pc = 0; pc < 3; ++pc) {
        const uint32_t st = sb + pc * STAGE_B;
        const int k0 = pc * BK;
#pragma unroll
        for (int j = 0; j < 2; ++j)
            cp_async16(st + OFF_A + sA[j], g_A + gA[j] + k0);
#pragma unroll
        for (int j = 0; j < 3; ++j)
            if (j < 2 || bok) cp_async16(st + OFF_B + sB[j], g_W + gB[j] + k0);
        CP_COMMIT();
    }

    // ---- main loop ----
    for (int kc = 0; kc < NCHUNK; ++kc) {
        CP_WAIT2();          // stage kc resident (<=2 newer groups pending)
        __syncthreads();

        // issue stage kc+3 (its buffer was consumed in iter kc-1; all warps passed the sync)
        {
            const int kn = kc + 3;
            if (kn < NCHUNK) {
                const uint32_t st = sb + (kn % STAGES) * STAGE_B;
                const int k0 = kn * BK;
#pragma unroll
                for (int j = 0; j < 2; ++j)
                    cp_async16(st + OFF_A + sA[j], g_A + gA[j] + k0);
#pragma unroll
                for (int j = 0; j < 3; ++j)
                    if (j < 2 || bok) cp_async16(st + OFF_B + sB[j], g_W + gB[j] + k0);
            }
            CP_COMMIT();   // commit (possibly empty) to keep group accounting uniform
        }

        const uint32_t st = sb + (kc % STAGES) * STAGE_B;
#pragma unroll
        for (int s = 0; s < 2; ++s) {           // two k16 steps per BK=32
            uint32_t av[4][4], bv[5][2];
#pragma unroll
            for (int mi = 0; mi < 4; ++mi)
                ldsm_x4(av[mi], st + OFF_A + aoff + mi * 16 * PITCH_B + s * 32);
#pragma unroll
            for (int ni = 0; ni < 5; ++ni)
                ldsm_x2(bv[ni], st + OFF_B + boff + ni * 8 * PITCH_B + s * 32);
#pragma unroll
            for (int mi = 0; mi < 4; ++mi)
#pragma unroll
                for (int ni = 0; ni < 5; ++ni)
                    mma_fp16(acc[mi][ni], av[mi], bv[ni]);
        }
    }
    CP_WAIT0();
    __syncthreads();    // done with stage buffers -> reuse smem for epilogue

    // ---- spill accumulators to smem [128][160] (pitch 164 floats) ----
    float* sf = (float*)smem;
    {
        const int r0 = wm * 64 + (lane >> 2);
        const int c0 = wn * 40 + (lane & 3) * 2;
#pragma unroll
        for (int mi = 0; mi < 4; ++mi)
#pragma unroll
            for (int ni = 0; ni < 5; ++ni) {
                const int rr = r0 + mi * 16;
                const int cc = c0 + ni * 8;
                sf[rr * EPI_PITCH + cc]            = acc[mi][ni][0];
                sf[rr * EPI_PITCH + cc + 1]        = acc[mi][ni][1];
                sf[(rr + 8) * EPI_PITCH + cc]      = acc[mi][ni][2];
                sf[(rr + 8) * EPI_PITCH + cc + 1]  = acc[mi][ni][3];
            }
    }
    __syncthreads();

    // ---- fused LSTM epilogue: 128 rows x 32 h per CTA ----
    for (int i = tid; i < BM * 32; i += THREADS) {
        const int r  = i >> 5;          // local m row
        const int hl = i & 31;          // local h
        const int b  = m0 + r;
        const int h  = hb0 + hl;
        const float* row = sf + r * EPI_PITCH + hl * 5;

        float iv = 1.f / (1.f + __expf(-(row[0] + bg[h])));
        float fv = 1.f / (1.f + __expf(-(row[1] + bg[H_DIM + h])));
        float ov = 1.f / (1.f + __expf(-(row[2] + bg[2 * H_DIM + h])));
        float p0 = row[3] + bc[2 * h];
        float p1 = row[4] + bc[2 * h + 1];

        float gsum = s_b2;
#pragma unroll
        for (int k = 0; k < 32; ++k) {
            float4 w = wk[k];
            float hid = fmaxf(w.x * p0 + w.y * p1 + w.z, 0.f);
            gsum += w.w * hid;
        }

        float c = fv * c_prev[(size_t)b * H_DIM + h] + iv * gsum;
        out[(size_t)b * H_DIM + h] = ov * tanhf(c);
        out[(size_t)B_DIM * H_DIM + (size_t)b * H_DIM + h] = c;
    }
}

// ============================================================
// Launch
// ============================================================
extern "C" void kernel_launch(void* const* d_in, const int* in_sizes, int n_in,
                              void* d_out, int out_size) {
    const float* x      = (const float*)d_in[0];
    const float* h_prev = (const float*)d_in[1];
    const float* c_prev = (const float*)d_in[2];
    const float* Wg     = (const float*)d_in[3];
    const float* bg     = (const float*)d_in[4];
    const float* Wc     = (const float*)d_in[5];
    const float* bc     = (const float*)d_in[6];
    const float* W1     = (const float*)d_in[7];
    const float* b1     = (const float*)d_in[8];
    const float* W2     = (const float*)d_in[9];
    const float* b2     = (const float*)d_in[10];
    float* out = (float*)d_out;

    convA_kernel<<<(int)(((size_t)B_DIM * KK / 4 + 255) / 256), 256>>>(x, h_prev);
    convW_kernel<<<(int)(((size_t)NT * KK / 4 + 255) / 256), 256>>>(Wg, Wc);

    cudaFuncSetAttribute(gemm_fused_kernel,
                         cudaFuncAttributeMaxDynamicSharedMemorySize, SMEM_TOTAL);
    dim3 grid(H_DIM / 32, B_DIM / BM);   // 32 x 32 = 1024 CTAs
    gemm_fused_kernel<<<grid, THREADS, SMEM_TOTAL>>>(c_prev, bg, bc, W1, b1, W2, b2, out);
}

// round 12
// speedup vs baseline: 2.1152x; 1.0224x over previous
#include <cuda_runtime.h>
#include <cuda_fp16.h>
#include <cstdint>

// ============================================================
// Problem dims
// ============================================================
#define B_DIM 4096
#define IN_DIM 1024
#define H_DIM 1024
#define KK 2048            // IN + H (K of the GEMM)
#define NT 5120            // 5*H  (reordered: per-h tuple [i,f,o,c0,c1])

// GEMM tiling
#define BM 128
#define BN 80              // 16 h-tuples of 5 columns
#define BK 32
#define NCHUNK (KK / BK)   // 64
#define STAGES 4
#define THREADS 256

// smem: fp16 tiles with 40-element (80B) row pitch (conflict-free for LDSM)
#define PITCH_B 80
#define A_TILE_B (BM * PITCH_B)          // 10240
#define B_TILE_B (BN * PITCH_B)          // 6400
#define OFF_A 0
#define OFF_B A_TILE_B
#define STAGE_B (A_TILE_B + B_TILE_B)    // 16640
#define EPI_PITCH 84                     // floats, padded (80 cols)
// stages = 66560 >= epilogue 128*84*4 = 43008
#define SMEM_TOTAL (STAGES * STAGE_B)    // 66560

// ============================================================
// Scratch (__device__ globals: allocation-free rule)
// ============================================================
__device__ __half g_A[(size_t)B_DIM * KK];
__device__ __half g_W[(size_t)NT * KK];   // row n' = 5*h + j, j in {i,f,o,c0,c1}

// ============================================================
// PTX helpers (baseline-family ISA only: no 'a'-suffix features)
// ============================================================
__device__ __forceinline__ uint32_t smem_u32(const void* p) {
    uint32_t a;
    asm("{ .reg .u64 t; cvta.to.shared.u64 t, %1; cvt.u32.u64 %0, t; }"
        : "=r"(a) : "l"(p));
    return a;
}

__device__ __forceinline__ void cp_async16(uint32_t s, const void* g) {
    asm volatile("cp.async.cg.shared.global [%0], [%1], 16;" :: "r"(s), "l"(g));
}
#define CP_COMMIT() asm volatile("cp.async.commit_group;" ::: "memory")
#define CP_WAIT2()  asm volatile("cp.async.wait_group 2;" ::: "memory")
#define CP_WAIT0()  asm volatile("cp.async.wait_group 0;" ::: "memory")

__device__ __forceinline__ void ldsm_x4(uint32_t* r, uint32_t addr) {
    asm volatile("ldmatrix.sync.aligned.m8n8.x4.shared.b16 {%0,%1,%2,%3}, [%4];"
                 : "=r"(r[0]), "=r"(r[1]), "=r"(r[2]), "=r"(r[3]) : "r"(addr));
}
__device__ __forceinline__ void ldsm_x2(uint32_t* r, uint32_t addr) {
    asm volatile("ldmatrix.sync.aligned.m8n8.x2.shared.b16 {%0,%1}, [%2];"
                 : "=r"(r[0]), "=r"(r[1]) : "r"(addr));
}
__device__ __forceinline__ void mma_fp16(float* c, const uint32_t* a, const uint32_t* b) {
    asm volatile(
        "mma.sync.aligned.m16n8k16.row.col.f32.f16.f16.f32 "
        "{%0,%1,%2,%3}, {%4,%5,%6,%7}, {%8,%9}, {%0,%1,%2,%3};"
        : "+f"(c[0]), "+f"(c[1]), "+f"(c[2]), "+f"(c[3])
        : "r"(a[0]), "r"(a[1]), "r"(a[2]), "r"(a[3]), "r"(b[0]), "r"(b[1]));
}

// round float4 -> 4 fp16 packed in uint2
__device__ __forceinline__ uint2 round4h(float4 v) {
    __half2 a = __halves2half2(__float2half(v.x), __float2half(v.y));
    __half2 b = __halves2half2(__float2half(v.z), __float2half(v.w));
    uint2 o;
    o.x = *(uint32_t*)&a; o.y = *(uint32_t*)&b;
    return o;
}

// ============================================================
// Kernel 1a: round combined [x | h_prev] to fp16, K-major
// ============================================================
__global__ __launch_bounds__(256)
void convA_kernel(const float* __restrict__ x, const float* __restrict__ h) {
    size_t i = (size_t)blockIdx.x * 256 + threadIdx.x;      // over B*KK/4
    if (i >= (size_t)B_DIM * KK / 4) return;
    size_t b  = i / (KK / 4);
    int    k4 = (int)(i % (KK / 4)) * 4;
    float4 v = (k4 < IN_DIM)
             ? *(const float4*)(x + b * IN_DIM + k4)
             : *(const float4*)(h + b * H_DIM + (k4 - IN_DIM));
    *(uint2*)(g_A + b * KK + k4) = round4h(v);
}

// Kernel 1b: fp16-round + REORDER W.  Row n' = 5*h + j:
//   j=0,1,2 -> Wg[j*1024 + h],  j=3,4 -> Wc[2*h + (j-3)]
__global__ __launch_bounds__(256)
void convW_kernel(const float* __restrict__ Wg, const float* __restrict__ Wc) {
    size_t i = (size_t)blockIdx.x * 256 + threadIdx.x;      // over NT*KK/4
    if (i >= (size_t)NT * KK / 4) return;
    size_t np = i / (KK / 4);
    int    k4 = (int)(i % (KK / 4)) * 4;
    int    hh = (int)(np / 5);
    int    j  = (int)(np % 5);
    const float* src = (j < 3) ? (Wg + ((size_t)j * H_DIM + hh) * KK + k4)
                               : (Wc + ((size_t)2 * hh + (j - 3)) * KK + k4);
    *(uint2*)(g_W + np * KK + k4) = round4h(*(const float4*)src);
}

// ============================================================
// Kernel 2: fused GEMM (HMMA, 1-pass fp16) + LSTM epilogue
//   2 CTAs/SM: BM=128 x BN=80, 8 warps (4 M x 2 N), warp tile 32x40
// ============================================================
__global__ __launch_bounds__(THREADS, 2)
void gemm_fused_kernel(const float* __restrict__ c_prev,
                       const float* __restrict__ bg, const float* __restrict__ bc,
                       const float* __restrict__ W1, const float* __restrict__ b1,
                       const float* __restrict__ W2, const float* __restrict__ b2,
                       float* __restrict__ out) {
    extern __shared__ __align__(128) char smem[];
    __shared__ float4 wk[32];     // {W1[k,0], W1[k,1], b1[k], W2[k]}
    __shared__ float  s_b2;

    const uint32_t sb = smem_u32(smem);
    const int tid  = threadIdx.x;
    const int wid  = tid >> 5;
    const int lane = tid & 31;
    const int wm   = wid >> 1;          // 0..3  (M warps, 32 rows each)
    const int wn   = wid & 1;           // 0..1  (N warps, 40 cols each)
    const int m0   = blockIdx.y * BM;
    const int hb0  = blockIdx.x * 16;   // first h of this CTA (16 tuples)
    const int n0   = hb0 * 5;           // first W' row

    if (tid < 32) wk[tid] = make_float4(W1[2 * tid], W1[2 * tid + 1], b1[tid], W2[tid]);
    if (tid == 0) s_b2 = b2[0];

    // ---- cp.async source/dest offsets (per thread) ----
    // A: 512 vec16 per tile (128 rows x 4); B: 320 (80 x 4).
    // smem row pitch 80B -> rows 0..7 mod 128B = {0,80,32,112,64,16,96,48}: LDSM conflict-free.
    uint32_t sA[2]; size_t gA[2];
#pragma unroll
    for (int j = 0; j < 2; ++j) {
        int v = tid + j * 256;                  // 0..511
        int r = v >> 2, c = v & 3;
        sA[j] = (uint32_t)(r * PITCH_B + c * 16);
        gA[j] = (size_t)(m0 + r) * KK + c * 8;
    }
    uint32_t sB[2]; size_t gB[2];
#pragma unroll
    for (int j = 0; j < 2; ++j) {
        int v = tid + j * 256;                  // 0..511 (guard < 320)
        int r = v >> 2, c = v & 3;
        sB[j] = (uint32_t)(r * PITCH_B + c * 16);
        gB[j] = (size_t)(n0 + r) * KK + c * 8;
    }
    const bool bok = (tid < 64);                // j==1 guard (256+tid < 320)

    // ---- LDSM base addresses ----
    // A frag (mi, s): addr = stage + aoff + mi*16*80 + s*32   (mi 0..1 over 32 rows)
    const uint32_t aoff = (uint32_t)((wm * 32 + (lane & 15)) * PITCH_B + (lane >> 4) * 16);
    // B frag (ni, s): addr = stage + OFF_B + boff + ni*8*80 + s*32
    const uint32_t boff = (uint32_t)((wn * 40 + (lane & 7)) * PITCH_B + ((lane >> 3) & 1) * 16);

    float acc[2][5][4];
#pragma unroll
    for (int mi = 0; mi < 2; ++mi)
#pragma unroll
        for (int ni = 0; ni < 5; ++ni)
#pragma unroll
            for (int q = 0; q < 4; ++q) acc[mi][ni][q] = 0.f;

    // ---- pipeline prologue: stages 0..2 ----
#pragma unroll
    for (int pc = 0; pc < 3; ++pc) {
        const uint32_t st = sb + pc * STAGE_B;
        const int k0 = pc * BK;
#pragma unroll
        for (int j = 0; j < 2; ++j)
            cp_async16(st + OFF_A + sA[j], g_A + gA[j] + k0);
        cp_async16(st + OFF_B + sB[0], g_W + gB[0] + k0);
        if (bok) cp_async16(st + OFF_B + sB[1], g_W + gB[1] + k0);
        CP_COMMIT();
    }

    // ---- main loop ----
    for (int kc = 0; kc < NCHUNK; ++kc) {
        CP_WAIT2();          // stage kc resident (<=2 newer groups pending)
        __syncthreads();

        // issue stage kc+3 (its buffer was consumed in iter kc-1; all warps passed the sync)
        {
            const int kn = kc + 3;
            if (kn < NCHUNK) {
                const uint32_t st = sb + (kn % STAGES) * STAGE_B;
                const int k0 = kn * BK;
#pragma unroll
                for (int j = 0; j < 2; ++j)
                    cp_async16(st + OFF_A + sA[j], g_A + gA[j] + k0);
                cp_async16(st + OFF_B + sB[0], g_W + gB[0] + k0);
                if (bok) cp_async16(st + OFF_B + sB[1], g_W + gB[1] + k0);
            }
            CP_COMMIT();   // commit (possibly empty) to keep group accounting uniform
        }

        const uint32_t st = sb + (kc % STAGES) * STAGE_B;
#pragma unroll
        for (int s = 0; s < 2; ++s) {           // two k16 steps per BK=32
            uint32_t av[2][4], bv[5][2];
#pragma unroll
            for (int mi = 0; mi < 2; ++mi)
                ldsm_x4(av[mi], st + OFF_A + aoff + mi * 16 * PITCH_B + s * 32);
#pragma unroll
            for (int ni = 0; ni < 5; ++ni)
                ldsm_x2(bv[ni], st + OFF_B + boff + ni * 8 * PITCH_B + s * 32);
#pragma unroll
            for (int mi = 0; mi < 2; ++mi)
#pragma unroll
                for (int ni = 0; ni < 5; ++ni)
                    mma_fp16(acc[mi][ni], av[mi], bv[ni]);
        }
    }
    CP_WAIT0();
    __syncthreads();    // done with stage buffers -> reuse smem for epilogue

    // ---- spill accumulators to smem [128][80] (pitch 84 floats) ----
    float* sf = (float*)smem;
    {
        const int r0 = wm * 32 + (lane >> 2);
        const int c0 = wn * 40 + (lane & 3) * 2;
#pragma unroll
        for (int mi = 0; mi < 2; ++mi)
#pragma unroll
            for (int ni = 0; ni < 5; ++ni) {
                const int rr = r0 + mi * 16;
                const int cc = c0 + ni * 8;
                sf[rr * EPI_PITCH + cc]            = acc[mi][ni][0];
                sf[rr * EPI_PITCH + cc + 1]        = acc[mi][ni][1];
                sf[(rr + 8) * EPI_PITCH + cc]      = acc[mi][ni][2];
                sf[(rr + 8) * EPI_PITCH + cc + 1]  = acc[mi][ni][3];
            }
    }
    __syncthreads();

    // ---- fused LSTM epilogue: 128 rows x 16 h per CTA ----
    for (int i = tid; i < BM * 16; i += THREADS) {
        const int r  = i >> 4;          // local m row
        const int hl = i & 15;          // local h
        const int b  = m0 + r;
        const int h  = hb0 + hl;
        const float* row = sf + r * EPI_PITCH + hl * 5;

        float iv = 1.f / (1.f + __expf(-(row[0] + bg[h])));
        float fv = 1.f / (1.f + __expf(-(row[1] + bg[H_DIM + h])));
        float ov = 1.f / (1.f + __expf(-(row[2] + bg[2 * H_DIM + h])));
        float p0 = row[3] + bc[2 * h];
        float p1 = row[4] + bc[2 * h + 1];

        float gsum = s_b2;
#pragma unroll
        for (int k = 0; k < 32; ++k) {
            float4 w = wk[k];
            float hid = fmaxf(w.x * p0 + w.y * p1 + w.z, 0.f);
            gsum += w.w * hid;
        }

        float c = fv * c_prev[(size_t)b * H_DIM + h] + iv * gsum;
        out[(size_t)b * H_DIM + h] = ov * tanhf(c);
        out[(size_t)B_DIM * H_DIM + (size_t)b * H_DIM + h] = c;
    }
}

// ============================================================
// Launch
// ============================================================
extern "C" void kernel_launch(void* const* d_in, const int* in_sizes, int n_in,
                              void* d_out, int out_size) {
    const float* x      = (const float*)d_in[0];
    const float* h_prev = (const float*)d_in[1];
    const float* c_prev = (const float*)d_in[2];
    const float* Wg     = (const float*)d_in[3];
    const float* bg     = (const float*)d_in[4];
    const float* Wc     = (const float*)d_in[5];
    const float* bc     = (const float*)d_in[6];
    const float* W1     = (const float*)d_in[7];
    const float* b1     = (const float*)d_in[8];
    const float* W2     = (const float*)d_in[9];
    const float* b2     = (const float*)d_in[10];
    float* out = (float*)d_out;

    convA_kernel<<<(int)(((size_t)B_DIM * KK / 4 + 255) / 256), 256>>>(x, h_prev);
    convW_kernel<<<(int)(((size_t)NT * KK / 4 + 255) / 256), 256>>>(Wg, Wc);

    cudaFuncSetAttribute(gemm_fused_kernel,
                         cudaFuncAttributeMaxDynamicSharedMemorySize, SMEM_TOTAL);
    dim3 grid(H_DIM / 16, B_DIM / BM);   // 64 x 32 = 2048 CTAs
    gemm_fused_kernel<<<grid, THREADS, SMEM_TOTAL>>>(c_prev, bg, bc, W1, b1, W2, b2, out);
}